// round 11
// baseline (speedup 1.0000x reference)
#include <cuda_runtime.h>
#include <math.h>
#include <stdint.h>

#define BMAX 8192
#define TILE 128
#define SMS  68                                  // smem row stride (u32), conflict-free
#define NTMAX (BMAX / TILE)                      // 64
#define NPAIR_MAX (NTMAX * (NTMAX + 1) / 2)      // 2080
#define NBLK8_MAX (BMAX / 8)                     // 1024

__device__ float g_pair_partial[NPAIR_MAX];
__device__ float g_ce_partial[NBLK8_MAX];
__device__ float g_qua_partial[NBLK8_MAX];
__device__ unsigned g_cnt = 0;

__device__ __forceinline__ unsigned f2tf32(float x) {
    unsigned u;
    asm("cvt.rna.tf32.f32 %0, %1;" : "=r"(u) : "f"(x));
    return u;
}

__device__ __forceinline__ void mma_tf32(float* c, const unsigned* a, const unsigned* b) {
    asm volatile(
        "mma.sync.aligned.m16n8k8.row.col.f32.tf32.tf32.f32 "
        "{%0,%1,%2,%3}, {%4,%5,%6,%7}, {%8,%9}, {%0,%1,%2,%3};\n"
        : "+f"(c[0]), "+f"(c[1]), "+f"(c[2]), "+f"(c[3])
        : "r"(a[0]), "r"(a[1]), "r"(a[2]), "r"(a[3]), "r"(b[0]), "r"(b[1]));
}

extern __shared__ unsigned dyn_smem[];   // As[128][SMS], Bs[128][SMS] (tf32 bits)

// ---------------------------------------------------------------------------
// One fused kernel:
//   blocks [0, naux)           : qua-BCE + CE(Yi) + CE(Ym), one warp per row
//   blocks [naux, naux+npair)  : 128x128 upper-tri pair tiles via tf32 mma.sync
//   last finishing block       : deterministic double-precision final combine
// ---------------------------------------------------------------------------
__global__ void __launch_bounds__(256, 2)
fused_kernel(const float* __restrict__ Fi,
             const float* __restrict__ Yi, const float* __restrict__ Ym,
             const int* __restrict__ y,
             int B, int C, int BITS, int NT, int npair, int naux,
             float* __restrict__ out) {
    __shared__ float sqI[TILE], sqJ[TILE];
    __shared__ int   yI[TILE],  yJ[TILE];
    __shared__ float red[8];
    __shared__ float aux_q[8], aux_l[8];
    __shared__ bool  amLast;
    __shared__ double dred[8];

    int tid  = threadIdx.x;
    int lane = tid & 31;
    int wid  = tid >> 5;

    if (blockIdx.x < (unsigned)naux) {
        // ----------------- aux block: qua + CE, one warp per row -----------------
        int gwarp = blockIdx.x * 8 + wid;
        float qua = 0.f, loss = 0.f;
        if (gwarp < B) {
            const float* row = Fi + (size_t)gwarp * BITS;
            for (int c = lane; c < BITS; c += 32) {
                float p  = row[c];
                float lp = fmaxf(logf(p), -100.f);
                float l1 = fmaxf(log1pf(-p), -100.f);
                qua += -(p * lp + (1.f - p) * l1);
            }
            int label = y[gwarp];
            #pragma unroll
            for (int m = 0; m < 2; m++) {
                const float* r2 = (m ? Ym : Yi) + (size_t)gwarp * C;
                float mx = -INFINITY;
                for (int c = lane; c < C; c += 32) mx = fmaxf(mx, r2[c]);
                #pragma unroll
                for (int o = 16; o; o >>= 1) mx = fmaxf(mx, __shfl_xor_sync(0xFFFFFFFFu, mx, o));
                float se = 0.f;
                for (int c = lane; c < C; c += 32) se += expf(r2[c] - mx);
                #pragma unroll
                for (int o = 16; o; o >>= 1) se += __shfl_xor_sync(0xFFFFFFFFu, se, o);
                loss += logf(se) + mx - r2[label];
            }
            // qua holds per-lane partials -> reduce. loss is warp-uniform -> DO NOT.
            #pragma unroll
            for (int o = 16; o; o >>= 1)
                qua += __shfl_down_sync(0xFFFFFFFFu, qua, o);
        }
        if (lane == 0) { aux_q[wid] = qua; aux_l[wid] = loss; }
        __syncthreads();
        if (tid == 0) {
            float tq = 0.f, tl = 0.f;
            #pragma unroll
            for (int i = 0; i < 8; i++) { tq += aux_q[i]; tl += aux_l[i]; }
            g_qua_partial[blockIdx.x] = tq;
            g_ce_partial[blockIdx.x]  = tl;
        }
    } else {
        // ----------------- pair block: tf32 tensor-core tile -----------------
        unsigned* As = dyn_smem;
        unsigned* Bs = dyn_smem + TILE * SMS;

        int t = blockIdx.x - naux;
        int bi = 0, rowlen = NT;
        while (t >= rowlen) { t -= rowlen; bi++; rowlen--; }
        int bj = bi + t;
        int i0 = bi * TILE, j0 = bj * TILE;
        bool diag = (bi == bj);

        int g  = lane >> 2;            // 0..7
        int tg = lane & 3;             // 0..3
        int warpM = (wid >> 2) * 64;   // 0 or 64
        int warpN = (wid & 3) * 32;    // 0,32,64,96

        // per-block squared norms from raw fp32
        {
            int r = tid & 127;
            int isJ = tid >> 7;                 // 0 -> I rows, 1 -> J rows
            int grow = (isJ ? j0 : i0) + r;
            const float* rp = Fi + (size_t)grow * BITS;
            float s = 0.f;
            #pragma unroll
            for (int q = 0; q < 16; q++) {
                float4 v = *(const float4*)(rp + q * 4);
                s += v.x * v.x + v.y * v.y + v.z * v.z + v.w * v.w;
            }
            if (isJ) { sqJ[r] = s; yJ[r] = y[grow]; }
            else     { sqI[r] = s; yI[r] = y[grow]; }
        }

        // load + convert both tiles (128 rows x 64 cols each)
        #pragma unroll
        for (int q = tid; q < TILE * 16; q += 256) {
            int row = q >> 4, quad = (q & 15) * 4;
            float4 a = *(const float4*)(Fi + (size_t)(i0 + row) * BITS + quad);
            unsigned* d = As + row * SMS + quad;
            d[0] = f2tf32(a.x); d[1] = f2tf32(a.y); d[2] = f2tf32(a.z); d[3] = f2tf32(a.w);
            float4 b = *(const float4*)(Fi + (size_t)(j0 + row) * BITS + quad);
            unsigned* e = Bs + row * SMS + quad;
            e[0] = f2tf32(b.x); e[1] = f2tf32(b.y); e[2] = f2tf32(b.z); e[3] = f2tf32(b.w);
        }
        __syncthreads();

        float acc[4][4][4];
        #pragma unroll
        for (int mf = 0; mf < 4; mf++)
            #pragma unroll
            for (int nf = 0; nf < 4; nf++)
                #pragma unroll
                for (int c = 0; c < 4; c++) acc[mf][nf][c] = 0.f;

        #pragma unroll
        for (int k0 = 0; k0 < 64; k0 += 8) {
            unsigned a[4][4], b[4][2];
            #pragma unroll
            for (int mf = 0; mf < 4; mf++) {
                const unsigned* base = As + (warpM + mf * 16 + g) * SMS + k0 + tg;
                a[mf][0] = base[0];
                a[mf][1] = base[8 * SMS];
                a[mf][2] = base[4];
                a[mf][3] = base[8 * SMS + 4];
            }
            #pragma unroll
            for (int nf = 0; nf < 4; nf++) {
                const unsigned* base = Bs + (warpN + nf * 8 + g) * SMS + k0 + tg;
                b[nf][0] = base[0];
                b[nf][1] = base[4];
            }
            #pragma unroll
            for (int mf = 0; mf < 4; mf++)
                #pragma unroll
                for (int nf = 0; nf < 4; nf++)
                    mma_tf32(acc[mf][nf], a[mf], b[nf]);
        }

        // fused epilogue
        float local = 0.f;
        #pragma unroll
        for (int mf = 0; mf < 4; mf++) {
            int r0 = warpM + mf * 16 + g;
            int r1 = r0 + 8;
            float s0 = sqI[r0], s1 = sqI[r1];
            int   q0 = yI[r0],  q1 = yI[r1];
            #pragma unroll
            for (int nf = 0; nf < 4; nf++) {
                int c0 = warpN + nf * 8 + 2 * tg;
                int c1 = c0 + 1;
                float t0 = sqJ[c0], t1 = sqJ[c1];
                int   z0 = yJ[c0],  z1 = yJ[c1];
                const float* A = acc[mf][nf];
                float D00 = fmaxf(s0 + t0 - 2.f * A[0], 0.f);
                float D01 = fmaxf(s0 + t1 - 2.f * A[1], 0.f);
                float D10 = fmaxf(s1 + t0 - 2.f * A[2], 0.f);
                float D11 = fmaxf(s1 + t1 - 2.f * A[3], 0.f);
                float v00 = (q0 == z0) ? D00 : fmaxf(32.f - D00, 0.f);
                float v01 = (q0 == z1) ? D01 : fmaxf(32.f - D01, 0.f);
                float v10 = (q1 == z0) ? D10 : fmaxf(32.f - D10, 0.f);
                float v11 = (q1 == z1) ? D11 : fmaxf(32.f - D11, 0.f);
                if (diag) {
                    if (r0 >= c0) v00 = 0.f;
                    if (r0 >= c1) v01 = 0.f;
                    if (r1 >= c0) v10 = 0.f;
                    if (r1 >= c1) v11 = 0.f;
                }
                local += (v00 + v01) + (v10 + v11);
            }
        }

        #pragma unroll
        for (int o = 16; o; o >>= 1) local += __shfl_down_sync(0xFFFFFFFFu, local, o);
        if (lane == 0) red[wid] = local;
        __syncthreads();
        if (tid == 0) {
            float s = 0.f;
            #pragma unroll
            for (int w = 0; w < 8; w++) s += red[w];
            g_pair_partial[blockIdx.x - naux] = s;
        }
    }

    // ----------------- last-done block: deterministic final combine -----------------
    if (tid == 0) {
        __threadfence();
        unsigned prev = atomicAdd(&g_cnt, 1u);
        amLast = (prev == (unsigned)(npair + naux - 1));
    }
    __syncthreads();

    if (amLast) {
        __threadfence();
        double pair = 0.0, ce = 0.0, qua = 0.0;
        for (int i = tid; i < npair; i += 256) pair += (double)g_pair_partial[i];
        for (int i = tid; i < naux;  i += 256) {
            ce  += (double)g_ce_partial[i];
            qua += (double)g_qua_partial[i];
        }
        double invPair = 1.0 / (2.0 * (double)B * (double)(B - 1));
        double invB    = 1.0 / (double)B;
        double sclQ    = 0.1 / ((double)B * (double)BITS);
        double v = pair * invPair + ce * invB + qua * sclQ;
        #pragma unroll
        for (int o = 16; o; o >>= 1) v += __shfl_down_sync(0xFFFFFFFFu, v, o);
        if (lane == 0) dred[wid] = v;
        __syncthreads();
        if (tid == 0) {
            double s = 0.0;
            #pragma unroll
            for (int w = 0; w < 8; w++) s += dred[w];
            out[0] = (float)s;
            g_cnt = 0;   // reset for next graph replay
        }
    }
}

// ---------------------------------------------------------------------------
extern "C" void kernel_launch(void* const* d_in, const int* in_sizes, int n_in,
                              void* d_out, int out_size) {
    const float* Ym = (const float*)d_in[0];
    const float* Fi = (const float*)d_in[1];
    const float* Yi = (const float*)d_in[2];
    const int*   y  = (const int*)  d_in[3];

    int B    = in_sizes[3];
    int C    = in_sizes[0] / B;
    int BITS = in_sizes[1] / B;

    int naux  = (B + 7) / 8;
    int NT    = B / TILE;
    int npair = NT * (NT + 1) / 2;

    static int smem_set = -1;
    int dyn_bytes = 2 * TILE * SMS * sizeof(unsigned);   // 69632 B
    if (smem_set < 0) {
        cudaFuncSetAttribute(fused_kernel,
                             cudaFuncAttributeMaxDynamicSharedMemorySize, dyn_bytes);
        smem_set = 1;
    }

    fused_kernel<<<naux + npair, 256, dyn_bytes>>>(Fi, Yi, Ym, y,
                                                   B, C, BITS, NT, npair, naux,
                                                   (float*)d_out);
}

// round 15
// speedup vs baseline: 1.5845x; 1.5845x over previous
#include <cuda_runtime.h>
#include <math.h>
#include <stdint.h>

#define BMAX 8192
#define TILE 128
#define SMS  68                                  // smem row stride (u32), conflict-free
#define NTMAX (BMAX / TILE)                      // 64
#define NPAIR_MAX (NTMAX * (NTMAX + 1) / 2)      // 2080
#define NBLK8_MAX (BMAX / 8)                     // 1024

__device__ float g_sq[BMAX];
__device__ float g_pair_partial[NPAIR_MAX];
__device__ float g_ce_partial[NBLK8_MAX];
__device__ float g_qua_partial[NBLK8_MAX];
__device__ unsigned g_cnt = 0;

__device__ __forceinline__ unsigned f2tf32(float x) {
    unsigned u;
    asm("cvt.rna.tf32.f32 %0, %1;" : "=r"(u) : "f"(x));
    return u;
}

__device__ __forceinline__ void mma_tf32(float* c, const unsigned* a, const unsigned* b) {
    asm volatile(
        "mma.sync.aligned.m16n8k8.row.col.f32.tf32.tf32.f32 "
        "{%0,%1,%2,%3}, {%4,%5,%6,%7}, {%8,%9}, {%0,%1,%2,%3};\n"
        : "+f"(c[0]), "+f"(c[1]), "+f"(c[2]), "+f"(c[3])
        : "r"(a[0]), "r"(a[1]), "r"(a[2]), "r"(a[3]), "r"(b[0]), "r"(b[1]));
}

// ---------------------------------------------------------------------------
// Kernel 1 (lean, high occupancy): per-row sq norms + qua-BCE + CE(Yi,Ym).
// One warp per row.
// ---------------------------------------------------------------------------
__global__ void aux_kernel(const float* __restrict__ Fi,
                           const float* __restrict__ Yi, const float* __restrict__ Ym,
                           const int* __restrict__ y, int B, int C, int BITS) {
    int gwarp = (blockIdx.x * blockDim.x + threadIdx.x) >> 5;
    int lane  = threadIdx.x & 31;
    int wib   = threadIdx.x >> 5;

    float sq = 0.f, qua = 0.f, loss = 0.f;
    if (gwarp < B) {
        const float* row = Fi + (size_t)gwarp * BITS;
        for (int c = lane; c < BITS; c += 32) {
            float p  = row[c];
            sq += p * p;
            float lp = fmaxf(logf(p), -100.f);
            float l1 = fmaxf(log1pf(-p), -100.f);
            qua += -(p * lp + (1.f - p) * l1);
        }
        #pragma unroll
        for (int o = 16; o; o >>= 1) {
            sq  += __shfl_down_sync(0xFFFFFFFFu, sq,  o);
            qua += __shfl_down_sync(0xFFFFFFFFu, qua, o);
        }
        if (lane == 0) g_sq[gwarp] = sq;

        int label = y[gwarp];
        #pragma unroll
        for (int m = 0; m < 2; m++) {
            const float* r2 = (m ? Ym : Yi) + (size_t)gwarp * C;
            float mx = -INFINITY;
            for (int c = lane; c < C; c += 32) mx = fmaxf(mx, r2[c]);
            #pragma unroll
            for (int o = 16; o; o >>= 1) mx = fmaxf(mx, __shfl_xor_sync(0xFFFFFFFFu, mx, o));
            float se = 0.f;
            for (int c = lane; c < C; c += 32) se += expf(r2[c] - mx);
            #pragma unroll
            for (int o = 16; o; o >>= 1) se += __shfl_xor_sync(0xFFFFFFFFu, se, o);
            loss += logf(se) + mx - r2[label];   // warp-uniform
        }
    }
    __shared__ float sq_s[8], sl_s[8];
    if (lane == 0) { sq_s[wib] = qua; sl_s[wib] = loss; }
    __syncthreads();
    if (threadIdx.x == 0) {
        float tq = 0.f, tl = 0.f;
        #pragma unroll
        for (int i = 0; i < 8; i++) { tq += sq_s[i]; tl += sl_s[i]; }
        g_qua_partial[blockIdx.x] = tq;
        g_ce_partial[blockIdx.x]  = tl;
    }
}

// ---------------------------------------------------------------------------
// Kernel 2: pairwise term via tf32 mma.sync, fused epilogue, and last-done
// block performing the deterministic final combine (replaces final_kernel).
// ---------------------------------------------------------------------------
extern __shared__ unsigned dyn_smem[];   // As[128][SMS], Bs[128][SMS]

__global__ void __launch_bounds__(256, 2)
pair_mma_kernel(const float* __restrict__ Fi, const int* __restrict__ y,
                int B, int BITS, int NT, int npair, int naux,
                float* __restrict__ out) {
    unsigned* As = dyn_smem;
    unsigned* Bs = dyn_smem + TILE * SMS;

    __shared__ float sqI[TILE], sqJ[TILE];
    __shared__ int   yI[TILE],  yJ[TILE];
    __shared__ float red[8];
    __shared__ bool  amLast;
    __shared__ double dred[8];

    // linear block -> (bi, bj) with bi <= bj
    int t = blockIdx.x;
    int bi = 0, rowlen = NT;
    while (t >= rowlen) { t -= rowlen; bi++; rowlen--; }
    int bj = bi + t;
    int i0 = bi * TILE, j0 = bj * TILE;
    bool diag = (bi == bj);

    int tid  = threadIdx.x;
    int lane = tid & 31;
    int wid  = tid >> 5;
    int g    = lane >> 2;
    int tg   = lane & 3;
    int warpM = (wid >> 2) * 64;
    int warpN = (wid & 3) * 32;

    if (tid < TILE) { sqI[tid] = g_sq[i0 + tid]; yI[tid] = y[i0 + tid]; }
    else            { int u = tid - TILE; sqJ[u] = g_sq[j0 + u]; yJ[u] = y[j0 + u]; }

    // load + convert both tiles (128 rows x 64 cols each), float4 reads
    #pragma unroll
    for (int q = tid; q < TILE * 16; q += 256) {
        int row = q >> 4, quad = (q & 15) * 4;
        float4 a = *(const float4*)(Fi + (size_t)(i0 + row) * BITS + quad);
        unsigned* d = As + row * SMS + quad;
        d[0] = f2tf32(a.x); d[1] = f2tf32(a.y); d[2] = f2tf32(a.z); d[3] = f2tf32(a.w);
        float4 b = *(const float4*)(Fi + (size_t)(j0 + row) * BITS + quad);
        unsigned* e = Bs + row * SMS + quad;
        e[0] = f2tf32(b.x); e[1] = f2tf32(b.y); e[2] = f2tf32(b.z); e[3] = f2tf32(b.w);
    }
    __syncthreads();

    float acc[4][4][4];
    #pragma unroll
    for (int mf = 0; mf < 4; mf++)
        #pragma unroll
        for (int nf = 0; nf < 4; nf++)
            #pragma unroll
            for (int c = 0; c < 4; c++) acc[mf][nf][c] = 0.f;

    #pragma unroll
    for (int k0 = 0; k0 < 64; k0 += 8) {
        unsigned a[4][4], b[4][2];
        #pragma unroll
        for (int mf = 0; mf < 4; mf++) {
            const unsigned* base = As + (warpM + mf * 16 + g) * SMS + k0 + tg;
            a[mf][0] = base[0];
            a[mf][1] = base[8 * SMS];
            a[mf][2] = base[4];
            a[mf][3] = base[8 * SMS + 4];
        }
        #pragma unroll
        for (int nf = 0; nf < 4; nf++) {
            const unsigned* base = Bs + (warpN + nf * 8 + g) * SMS + k0 + tg;
            b[nf][0] = base[0];
            b[nf][1] = base[4];
        }
        #pragma unroll
        for (int mf = 0; mf < 4; mf++)
            #pragma unroll
            for (int nf = 0; nf < 4; nf++)
                mma_tf32(acc[mf][nf], a[mf], b[nf]);
    }

    // fused epilogue
    float local = 0.f;
    #pragma unroll
    for (int mf = 0; mf < 4; mf++) {
        int r0 = warpM + mf * 16 + g;
        int r1 = r0 + 8;
        float s0 = sqI[r0], s1 = sqI[r1];
        int   q0 = yI[r0],  q1 = yI[r1];
        #pragma unroll
        for (int nf = 0; nf < 4; nf++) {
            int c0 = warpN + nf * 8 + 2 * tg;
            int c1 = c0 + 1;
            float t0 = sqJ[c0], t1 = sqJ[c1];
            int   z0 = yJ[c0],  z1 = yJ[c1];
            const float* A = acc[mf][nf];
            float D00 = fmaxf(s0 + t0 - 2.f * A[0], 0.f);
            float D01 = fmaxf(s0 + t1 - 2.f * A[1], 0.f);
            float D10 = fmaxf(s1 + t0 - 2.f * A[2], 0.f);
            float D11 = fmaxf(s1 + t1 - 2.f * A[3], 0.f);
            float v00 = (q0 == z0) ? D00 : fmaxf(32.f - D00, 0.f);
            float v01 = (q0 == z1) ? D01 : fmaxf(32.f - D01, 0.f);
            float v10 = (q1 == z0) ? D10 : fmaxf(32.f - D10, 0.f);
            float v11 = (q1 == z1) ? D11 : fmaxf(32.f - D11, 0.f);
            if (diag) {
                if (r0 >= c0) v00 = 0.f;
                if (r0 >= c1) v01 = 0.f;
                if (r1 >= c0) v10 = 0.f;
                if (r1 >= c1) v11 = 0.f;
            }
            local += (v00 + v01) + (v10 + v11);
        }
    }

    #pragma unroll
    for (int o = 16; o; o >>= 1) local += __shfl_down_sync(0xFFFFFFFFu, local, o);
    if (lane == 0) red[wid] = local;
    __syncthreads();
    if (tid == 0) {
        float s = 0.f;
        #pragma unroll
        for (int w = 0; w < 8; w++) s += red[w];
        g_pair_partial[blockIdx.x] = s;
        __threadfence();
        unsigned prev = atomicAdd(&g_cnt, 1u);
        amLast = (prev == (unsigned)(npair - 1));
    }
    __syncthreads();

    // last-done block: fixed-order deterministic final combine in double
    if (amLast) {
        __threadfence();
        double pair = 0.0, ce = 0.0, qua = 0.0;
        for (int i = tid; i < npair; i += 256) pair += (double)g_pair_partial[i];
        for (int i = tid; i < naux;  i += 256) {
            ce  += (double)g_ce_partial[i];
            qua += (double)g_qua_partial[i];
        }
        double invPair = 1.0 / (2.0 * (double)B * (double)(B - 1));
        double invB    = 1.0 / (double)B;
        double sclQ    = 0.1 / ((double)B * (double)BITS);
        double v = pair * invPair + ce * invB + qua * sclQ;
        #pragma unroll
        for (int o = 16; o; o >>= 1) v += __shfl_down_sync(0xFFFFFFFFu, v, o);
        if (lane == 0) dred[wid] = v;
        __syncthreads();
        if (tid == 0) {
            double s = 0.0;
            #pragma unroll
            for (int w = 0; w < 8; w++) s += dred[w];
            out[0] = (float)s;
            g_cnt = 0;   // reset for next graph replay
        }
    }
}

// ---------------------------------------------------------------------------
extern "C" void kernel_launch(void* const* d_in, const int* in_sizes, int n_in,
                              void* d_out, int out_size) {
    const float* Ym = (const float*)d_in[0];
    const float* Fi = (const float*)d_in[1];
    const float* Yi = (const float*)d_in[2];
    const int*   y  = (const int*)  d_in[3];

    int B    = in_sizes[3];
    int C    = in_sizes[0] / B;
    int BITS = in_sizes[1] / B;

    int naux  = (B + 7) / 8;
    int NT    = B / TILE;
    int npair = NT * (NT + 1) / 2;

    static int smem_set = -1;
    int dyn_bytes = 2 * TILE * SMS * sizeof(unsigned);   // 69632 B
    if (smem_set < 0) {
        cudaFuncSetAttribute(pair_mma_kernel,
                             cudaFuncAttributeMaxDynamicSharedMemorySize, dyn_bytes);
        smem_set = 1;
    }

    aux_kernel<<<naux, 256>>>(Fi, Yi, Ym, y, B, C, BITS);
    pair_mma_kernel<<<npair, 256, dyn_bytes>>>(Fi, y, B, BITS, NT, npair, naux,
                                               (float*)d_out);
}